// round 13
// baseline (speedup 1.0000x reference)
#include <cuda_runtime.h>
#include <cuda_fp16.h>
#include <cstdint>

#define NMAX 100000
#define EMAX 3200000
#define FOUT 64
#define FIN  256

// ---------- device scratch (static; no allocation allowed) ----------
__device__ __half2 g_hh[NMAX * 32];       // projected features, fp16 (half2 per 2 feats)
__device__ float g_asrc[NMAX];
__device__ float g_adst[NMAX];
__device__ int   g_cnt[NMAX];             // in-degree histogram
__device__ int   g_cur[NMAX];             // reorder cursors (pre-seeded with row start)
__device__ int   g_start[NMAX + 1];       // CSR row offsets (by dst)
__device__ int   g_bsum[256];             // scan block sums
__device__ int2  g_csr[EMAX];             // (src, bits(p)) per edge, grouped by dst

// ---------------- packed f32x2 helpers ----------------
__device__ __forceinline__ unsigned long long f32x2_fma(
    unsigned long long a, unsigned long long b, unsigned long long c) {
    unsigned long long d;
    asm("fma.rn.f32x2 %0, %1, %2, %3;" : "=l"(d) : "l"(a), "l"(b), "l"(c));
    return d;
}
__device__ __forceinline__ unsigned long long f32_dup(float v) {
    unsigned long long d;
    asm("mov.b64 %0, {%1, %1};" : "=l"(d) : "f"(v));
    return d;
}
__device__ __forceinline__ float2 f32x2_unpack(unsigned long long v) {
    float lo, hi;
    asm("mov.b64 {%0, %1}, %2;" : "=f"(lo), "=f"(hi) : "l"(v));
    return make_float2(lo, hi);
}

// ---------------- init: zero histogram ----------------
__global__ void k_init(int n) {
    int i = blockIdx.x * blockDim.x + threadIdx.x;
    if (i < n) g_cnt[i] = 0;
}

// ---------------- GEMM: h = x @ W with packed FFMA2 -------------------------
// CTA = 128 nodes x 64 feats, 256 threads, K chunked by 64.
// thread (tf = t&7 -> feats 8tf..8tf+7 as 4 f32x2 pairs; tn = t>>3 -> nodes 4tn..4tn+3)
#define XS_STRIDE 132
__global__ __launch_bounds__(256) void k_gemm(
    const float* __restrict__ x, const float* __restrict__ W,
    const float* __restrict__ att_src, const float* __restrict__ att_dst, int n)
{
    __shared__ float ws[64 * 64];              // [k][f]       16KB
    __shared__ float xs[64 * XS_STRIDE];       // [k][node]    33.8KB

    const int t  = threadIdx.x;
    const int tf = t & 7;          // feature pair group: pairs 4tf..4tf+3
    const int tn = t >> 3;         // node group: nodes 4tn..4tn+3
    const int tile0 = blockIdx.x * 128;

    unsigned long long acc[4][4];  // [node][fpair]
#pragma unroll
    for (int i = 0; i < 4; i++)
#pragma unroll
        for (int j = 0; j < 4; j++) acc[i][j] = 0ull;

    const int kk = t & 63;         // k-column for x fill
    for (int kc = 0; kc < 4; kc++) {
        const int k0 = kc * 64;
        // fill W tile [64k][64f], linear coalesced
#pragma unroll
        for (int i = t; i < 4096; i += 256) ws[i] = W[k0 * 64 + i];
        // fill x tile transposed: xs[k][node]
#pragma unroll
        for (int nn = (t >> 6); nn < 128; nn += 4) {
            int node = tile0 + nn;
            float v = (node < n) ? x[(size_t)node * FIN + k0 + kk] : 0.f;
            xs[kk * XS_STRIDE + nn] = v;
        }
        __syncthreads();

#pragma unroll 4
        for (int k = 0; k < 64; k++) {
            // W pairs: feats 8tf..8tf+7 -> 4 x f32x2 (two 16B LDS)
            const ulonglong2 wA = *(const ulonglong2*)(ws + k * 64 + 8 * tf);
            const ulonglong2 wB = *(const ulonglong2*)(ws + k * 64 + 8 * tf + 4);
            // x: 4 nodes (one 16B LDS)
            const float4 xv = *(const float4*)(xs + k * XS_STRIDE + 4 * tn);

            unsigned long long x0 = f32_dup(xv.x);
            unsigned long long x1 = f32_dup(xv.y);
            unsigned long long x2 = f32_dup(xv.z);
            unsigned long long x3 = f32_dup(xv.w);

            acc[0][0] = f32x2_fma(x0, wA.x, acc[0][0]);
            acc[0][1] = f32x2_fma(x0, wA.y, acc[0][1]);
            acc[0][2] = f32x2_fma(x0, wB.x, acc[0][2]);
            acc[0][3] = f32x2_fma(x0, wB.y, acc[0][3]);
            acc[1][0] = f32x2_fma(x1, wA.x, acc[1][0]);
            acc[1][1] = f32x2_fma(x1, wA.y, acc[1][1]);
            acc[1][2] = f32x2_fma(x1, wB.x, acc[1][2]);
            acc[1][3] = f32x2_fma(x1, wB.y, acc[1][3]);
            acc[2][0] = f32x2_fma(x2, wA.x, acc[2][0]);
            acc[2][1] = f32x2_fma(x2, wA.y, acc[2][1]);
            acc[2][2] = f32x2_fma(x2, wB.x, acc[2][2]);
            acc[2][3] = f32x2_fma(x2, wB.y, acc[2][3]);
            acc[3][0] = f32x2_fma(x3, wA.x, acc[3][0]);
            acc[3][1] = f32x2_fma(x3, wA.y, acc[3][1]);
            acc[3][2] = f32x2_fma(x3, wB.x, acc[3][2]);
            acc[3][3] = f32x2_fma(x3, wB.y, acc[3][3]);
        }
        __syncthreads();
    }

    // epilogue: per node -> 8 feats, fused att dots + fp16 store
    const int f0 = 8 * tf;
    float as_w[8], ad_w[8];
#pragma unroll
    for (int j = 0; j < 8; j++) {
        as_w[j] = __ldg(att_src + f0 + j);
        ad_w[j] = __ldg(att_dst + f0 + j);
    }

#pragma unroll
    for (int i = 0; i < 4; i++) {
        int node = tile0 + 4 * tn + i;
        float2 p0 = f32x2_unpack(acc[i][0]);
        float2 p1 = f32x2_unpack(acc[i][1]);
        float2 p2 = f32x2_unpack(acc[i][2]);
        float2 p3 = f32x2_unpack(acc[i][3]);

        float as = p0.x * as_w[0] + p0.y * as_w[1] + p1.x * as_w[2] + p1.y * as_w[3]
                 + p2.x * as_w[4] + p2.y * as_w[5] + p3.x * as_w[6] + p3.y * as_w[7];
        float ad = p0.x * ad_w[0] + p0.y * ad_w[1] + p1.x * ad_w[2] + p1.y * ad_w[3]
                 + p2.x * ad_w[4] + p2.y * ad_w[5] + p3.x * ad_w[6] + p3.y * ad_w[7];
        // reduce over the 8 tf lanes (lanes differing in bits 0..2)
#pragma unroll
        for (int off = 1; off < 8; off <<= 1) {
            as += __shfl_xor_sync(0xffffffffu, as, off);
            ad += __shfl_xor_sync(0xffffffffu, ad, off);
        }

        if (node < n) {
            __half2 hv[4];
            hv[0] = __floats2half2_rn(p0.x, p0.y);
            hv[1] = __floats2half2_rn(p1.x, p1.y);
            hv[2] = __floats2half2_rn(p2.x, p2.y);
            hv[3] = __floats2half2_rn(p3.x, p3.y);
            // half2 slots 4tf..4tf+3 of node row (32 half2 per node); 16B aligned
            __half2* dst = g_hh + (size_t)node * 32 + 4 * tf;
            *(uint4*)dst = *(const uint4*)hv;
            if (tf == 0) { g_asrc[node] = as; g_adst[node] = ad; }
        }
    }
}

// ---------------- count in-degrees ----------------
__global__ void k_count(const int* __restrict__ dst, int e) {
    int i = blockIdx.x * blockDim.x + threadIdx.x;
    if (i < e) atomicAdd(&g_cnt[dst[i]], 1);
}

// ---------------- scan (3-phase exclusive prefix sum of g_cnt -> g_start) ----
__global__ void k_scanA(int n) {
    __shared__ int sm[256];
    const int t = threadIdx.x;
    const int base = blockIdx.x * 1024;
    const int i0 = base + t * 4;
    int v[4];
#pragma unroll
    for (int j = 0; j < 4; j++) v[j] = (i0 + j < n) ? g_cnt[i0 + j] : 0;
    int s = v[0] + v[1] + v[2] + v[3];
    sm[t] = s;
    __syncthreads();
#pragma unroll
    for (int off = 1; off < 256; off <<= 1) {
        int xv = (t >= off) ? sm[t - off] : 0;
        __syncthreads();
        sm[t] += xv;
        __syncthreads();
    }
    int run = sm[t] - s;
#pragma unroll
    for (int j = 0; j < 4; j++) {
        if (i0 + j < n) g_start[i0 + j] = run;
        run += v[j];
    }
    if (t == 255) g_bsum[blockIdx.x] = sm[255];
}

__global__ void k_scanB(int nb, int n) {
    if (threadIdx.x == 0) {
        int run = 0;
        for (int i = 0; i < nb; i++) { int v = g_bsum[i]; g_bsum[i] = run; run += v; }
        g_start[n] = run;
    }
}

__global__ void k_scanC(int n) {
    int i = blockIdx.x * blockDim.x + threadIdx.x;
    if (i < n) {
        int st = g_start[i] + g_bsum[i >> 10];
        g_start[i] = st;
        g_cur[i] = st;          // cursor pre-seeded with row start
    }
}

// ---------------- reorder edges into CSR, precompute p = exp(leakyrelu(e)) ----
__global__ void k_reorder(const int* __restrict__ src, const int* __restrict__ dst, int e) {
    int i = blockIdx.x * blockDim.x + threadIdx.x;
    if (i >= e) return;
    int s = src[i];
    int d = dst[i];
    int idx = atomicAdd(&g_cur[d], 1);
    float l = g_asrc[s] + g_adst[d];
    l = l > 0.f ? l : 0.2f * l;
    float p = __expf(l);
    g_csr[idx] = make_int2(s, __float_as_int(p));
}

// ---------------- aggregate: warp per destination node, fp16 gather ---------
__global__ __launch_bounds__(256) void k_agg(
    const float* __restrict__ bias, float* __restrict__ out, int n)
{
    const int warp = (blockIdx.x * blockDim.x + threadIdx.x) >> 5;
    const int lane = threadIdx.x & 31;
    if (warp >= n) return;
    const int d = warp;
    int e  = g_start[d];
    const int e1 = g_start[d + 1];

    float2 acc = make_float2(0.f, 0.f);
    float den = 0.f;

    for (; e + 4 <= e1; e += 4) {
        int2 sp0 = g_csr[e], sp1 = g_csr[e + 1], sp2 = g_csr[e + 2], sp3 = g_csr[e + 3];
        float p0 = __int_as_float(sp0.y), p1 = __int_as_float(sp1.y);
        float p2 = __int_as_float(sp2.y), p3 = __int_as_float(sp3.y);
        float2 v0 = __half22float2(g_hh[(size_t)sp0.x * 32 + lane]);
        float2 v1 = __half22float2(g_hh[(size_t)sp1.x * 32 + lane]);
        float2 v2 = __half22float2(g_hh[(size_t)sp2.x * 32 + lane]);
        float2 v3 = __half22float2(g_hh[(size_t)sp3.x * 32 + lane]);
        acc.x += p0 * v0.x; acc.y += p0 * v0.y;
        acc.x += p1 * v1.x; acc.y += p1 * v1.y;
        acc.x += p2 * v2.x; acc.y += p2 * v2.y;
        acc.x += p3 * v3.x; acc.y += p3 * v3.y;
        den += p0 + p1 + p2 + p3;
    }
    for (; e < e1; e++) {
        int2 sp = g_csr[e];
        float p = __int_as_float(sp.y);
        float2 v = __half22float2(g_hh[(size_t)sp.x * 32 + lane]);
        acc.x += p * v.x; acc.y += p * v.y;
        den += p;
    }

    // self loop
    float l = g_asrc[d] + g_adst[d];
    l = l > 0.f ? l : 0.2f * l;
    float ps = __expf(l);
    float2 vd = __half22float2(g_hh[(size_t)d * 32 + lane]);
    acc.x += ps * vd.x; acc.y += ps * vd.y;
    den  += ps;

    float inv = 1.0f / (den + 1e-16f);
    float2 b = ((const float2*)bias)[lane];
    float2 o = make_float2(acc.x * inv + b.x, acc.y * inv + b.y);
    ((float2*)(out + (size_t)d * FOUT))[lane] = o;
}

// ---------------- launch ----------------
extern "C" void kernel_launch(void* const* d_in, const int* in_sizes, int n_in,
                              void* d_out, int out_size)
{
    const float* x        = (const float*)d_in[0];
    const int*   ei       = (const int*)d_in[1];
    const float* W        = (const float*)d_in[2];
    const float* att_src  = (const float*)d_in[3];
    const float* att_dst  = (const float*)d_in[4];
    const float* bias     = (const float*)d_in[5];
    float* out = (float*)d_out;

    const int n = in_sizes[0] / FIN;
    const int e = in_sizes[1] / 2;
    const int* src = ei;
    const int* dst = ei + e;

    k_init<<<(n + 255) / 256, 256>>>(n);
    k_gemm<<<(n + 127) / 128, 256>>>(x, W, att_src, att_dst, n);
    k_count<<<(e + 255) / 256, 256>>>(dst, e);
    const int nb = (n + 1023) / 1024;
    k_scanA<<<nb, 256>>>(n);
    k_scanB<<<1, 32>>>(nb, n);
    k_scanC<<<(n + 255) / 256, 256>>>(n);
    k_reorder<<<(e + 255) / 256, 256>>>(src, dst, e);
    k_agg<<<(n * 32 + 255) / 256, 256>>>(bias, out, n);
}

// round 17
// speedup vs baseline: 1.2088x; 1.2088x over previous
#include <cuda_runtime.h>
#include <cuda_fp16.h>
#include <cstdint>

#define NMAX 100000
#define EMAX 3200000
#define FOUT 64
#define FIN  256

// ---------- device scratch (static; no allocation allowed) ----------
__device__ __half2 g_hh[NMAX * 32];       // projected features, fp16 (half2 per 2 feats)
__device__ float g_asrc[NMAX];
__device__ float g_adst[NMAX];
__device__ int   g_cnt[NMAX];             // in-degree histogram
__device__ int   g_cur[NMAX];             // reorder cursors (pre-seeded with row start)
__device__ int   g_start[NMAX + 1];       // CSR row offsets (by dst)
__device__ int   g_bsum[256];             // scan block sums
__device__ int2  g_csr[EMAX];             // (src, bits(p)) per edge, grouped by dst

// ---------------- init: zero histogram ----------------
__global__ void k_init(int n) {
    int i = blockIdx.x * blockDim.x + threadIdx.x;
    if (i < n) g_cnt[i] = 0;
}

// ---------------- GEMM: h = x @ W (round-4 proven fp32 version) -------------
// block = 256 threads, 64 nodes/block, k-chunked by 64.
// thread (tf = t%16, tn = t/16) computes 4 nodes x 4 features.
#define XS_STRIDE 68
__global__ __launch_bounds__(256) void k_gemm(
    const float* __restrict__ x, const float* __restrict__ W,
    const float* __restrict__ att_src, const float* __restrict__ att_dst, int n)
{
    __shared__ float ws[64 * 64];          // [k][f]
    __shared__ float xs[64 * XS_STRIDE];   // [k][node], padded

    const int t   = threadIdx.x;
    const int tf  = t & 15;        // feature group: f0 = 4*tf
    const int tn  = t >> 4;        // node group:    n0 = 4*tn
    const int node0 = blockIdx.x * 64;

    float acc[4][4];
#pragma unroll
    for (int i = 0; i < 4; i++)
#pragma unroll
        for (int j = 0; j < 4; j++) acc[i][j] = 0.f;

    const int kk = t & 63;         // for x loads
    for (int kc = 0; kc < 4; kc++) {
        const int k0 = kc * 64;
        // load W[k0:k0+64][0:64]
#pragma unroll
        for (int i = t; i < 4096; i += 256) ws[i] = W[k0 * 64 + i];
        // load x tile transposed: xs[k][node]
#pragma unroll
        for (int nn = (t >> 6); nn < 64; nn += 4) {
            int node = node0 + nn;
            float v = (node < n) ? x[node * FIN + k0 + kk] : 0.f;
            xs[kk * XS_STRIDE + nn] = v;
        }
        __syncthreads();
#pragma unroll 8
        for (int k = 0; k < 64; k++) {
            const float4 wv = *(const float4*)(ws + k * 64 + (tf << 2));
            const float4 xv = *(const float4*)(xs + k * XS_STRIDE + (tn << 2));
            acc[0][0] += xv.x * wv.x; acc[0][1] += xv.x * wv.y;
            acc[0][2] += xv.x * wv.z; acc[0][3] += xv.x * wv.w;
            acc[1][0] += xv.y * wv.x; acc[1][1] += xv.y * wv.y;
            acc[1][2] += xv.y * wv.z; acc[1][3] += xv.y * wv.w;
            acc[2][0] += xv.z * wv.x; acc[2][1] += xv.z * wv.y;
            acc[2][2] += xv.z * wv.z; acc[2][3] += xv.z * wv.w;
            acc[3][0] += xv.w * wv.x; acc[3][1] += xv.w * wv.y;
            acc[3][2] += xv.w * wv.z; acc[3][3] += xv.w * wv.w;
        }
        __syncthreads();
    }

    // epilogue: store h as fp16, reduce a_src/a_dst across the 16 feature-lanes
    const int f0 = tf << 2;
    float as0 = att_src[f0], as1 = att_src[f0 + 1], as2 = att_src[f0 + 2], as3 = att_src[f0 + 3];
    float ad0 = att_dst[f0], ad1 = att_dst[f0 + 1], ad2 = att_dst[f0 + 2], ad3 = att_dst[f0 + 3];

#pragma unroll
    for (int i = 0; i < 4; i++) {
        int node = node0 + (tn << 2) + i;
        float4 hv = make_float4(acc[i][0], acc[i][1], acc[i][2], acc[i][3]);
        float ps = hv.x * as0 + hv.y * as1 + hv.z * as2 + hv.w * as3;
        float pd = hv.x * ad0 + hv.y * ad1 + hv.z * ad2 + hv.w * ad3;
#pragma unroll
        for (int off = 1; off < 16; off <<= 1) {
            ps += __shfl_xor_sync(0xffffffffu, ps, off);
            pd += __shfl_xor_sync(0xffffffffu, pd, off);
        }
        if (node < n) {
            __half2 hv2[2];
            hv2[0] = __floats2half2_rn(hv.x, hv.y);
            hv2[1] = __floats2half2_rn(hv.z, hv.w);
            // half2 slots 2*tf, 2*tf+1 of node row (32 half2 per node); 8B aligned
            __half2* dst = g_hh + (size_t)node * 32 + 2 * tf;
            *(uint2*)dst = *(const uint2*)hv2;
            if (tf == 0) { g_asrc[node] = ps; g_adst[node] = pd; }
        }
    }
}

// ---------------- count in-degrees ----------------
__global__ void k_count(const int* __restrict__ dst, int e) {
    int i = blockIdx.x * blockDim.x + threadIdx.x;
    if (i < e) atomicAdd(&g_cnt[dst[i]], 1);
}

// ---------------- scan (3-phase exclusive prefix sum of g_cnt -> g_start) ----
__global__ void k_scanA(int n) {
    __shared__ int sm[256];
    const int t = threadIdx.x;
    const int base = blockIdx.x * 1024;
    const int i0 = base + t * 4;
    int v[4];
#pragma unroll
    for (int j = 0; j < 4; j++) v[j] = (i0 + j < n) ? g_cnt[i0 + j] : 0;
    int s = v[0] + v[1] + v[2] + v[3];
    sm[t] = s;
    __syncthreads();
#pragma unroll
    for (int off = 1; off < 256; off <<= 1) {
        int xv = (t >= off) ? sm[t - off] : 0;
        __syncthreads();
        sm[t] += xv;
        __syncthreads();
    }
    int run = sm[t] - s;
#pragma unroll
    for (int j = 0; j < 4; j++) {
        if (i0 + j < n) g_start[i0 + j] = run;
        run += v[j];
    }
    if (t == 255) g_bsum[blockIdx.x] = sm[255];
}

__global__ void k_scanB(int nb, int n) {
    if (threadIdx.x == 0) {
        int run = 0;
        for (int i = 0; i < nb; i++) { int v = g_bsum[i]; g_bsum[i] = run; run += v; }
        g_start[n] = run;
    }
}

__global__ void k_scanC(int n) {
    int i = blockIdx.x * blockDim.x + threadIdx.x;
    if (i < n) {
        int st = g_start[i] + g_bsum[i >> 10];
        g_start[i] = st;
        g_cur[i] = st;          // cursor pre-seeded with row start
    }
}

// ---------------- reorder edges into CSR, precompute p = exp(leakyrelu(e)) ----
__global__ void k_reorder(const int* __restrict__ src, const int* __restrict__ dst, int e) {
    int i = blockIdx.x * blockDim.x + threadIdx.x;
    if (i >= e) return;
    int s = src[i];
    int d = dst[i];
    int idx = atomicAdd(&g_cur[d], 1);
    float l = g_asrc[s] + g_adst[d];
    l = l > 0.f ? l : 0.2f * l;
    float p = __expf(l);
    g_csr[idx] = make_int2(s, __float_as_int(p));
}

// ---------------- aggregate: warp per destination node, fp16 gather ---------
__global__ __launch_bounds__(256) void k_agg(
    const float* __restrict__ bias, float* __restrict__ out, int n)
{
    const int warp = (blockIdx.x * blockDim.x + threadIdx.x) >> 5;
    const int lane = threadIdx.x & 31;
    if (warp >= n) return;
    const int d = warp;
    int e  = g_start[d];
    const int e1 = g_start[d + 1];

    float2 acc = make_float2(0.f, 0.f);
    float den = 0.f;

    for (; e + 4 <= e1; e += 4) {
        int2 sp0 = g_csr[e], sp1 = g_csr[e + 1], sp2 = g_csr[e + 2], sp3 = g_csr[e + 3];
        float p0 = __int_as_float(sp0.y), p1 = __int_as_float(sp1.y);
        float p2 = __int_as_float(sp2.y), p3 = __int_as_float(sp3.y);
        float2 v0 = __half22float2(g_hh[(size_t)sp0.x * 32 + lane]);
        float2 v1 = __half22float2(g_hh[(size_t)sp1.x * 32 + lane]);
        float2 v2 = __half22float2(g_hh[(size_t)sp2.x * 32 + lane]);
        float2 v3 = __half22float2(g_hh[(size_t)sp3.x * 32 + lane]);
        acc.x += p0 * v0.x; acc.y += p0 * v0.y;
        acc.x += p1 * v1.x; acc.y += p1 * v1.y;
        acc.x += p2 * v2.x; acc.y += p2 * v2.y;
        acc.x += p3 * v3.x; acc.y += p3 * v3.y;
        den += p0 + p1 + p2 + p3;
    }
    for (; e < e1; e++) {
        int2 sp = g_csr[e];
        float p = __int_as_float(sp.y);
        float2 v = __half22float2(g_hh[(size_t)sp.x * 32 + lane]);
        acc.x += p * v.x; acc.y += p * v.y;
        den += p;
    }

    // self loop
    float l = g_asrc[d] + g_adst[d];
    l = l > 0.f ? l : 0.2f * l;
    float ps = __expf(l);
    float2 vd = __half22float2(g_hh[(size_t)d * 32 + lane]);
    acc.x += ps * vd.x; acc.y += ps * vd.y;
    den  += ps;

    float inv = 1.0f / (den + 1e-16f);
    float2 b = ((const float2*)bias)[lane];
    float2 o = make_float2(acc.x * inv + b.x, acc.y * inv + b.y);
    ((float2*)(out + (size_t)d * FOUT))[lane] = o;
}

// ---------------- launch ----------------
extern "C" void kernel_launch(void* const* d_in, const int* in_sizes, int n_in,
                              void* d_out, int out_size)
{
    const float* x        = (const float*)d_in[0];
    const int*   ei       = (const int*)d_in[1];
    const float* W        = (const float*)d_in[2];
    const float* att_src  = (const float*)d_in[3];
    const float* att_dst  = (const float*)d_in[4];
    const float* bias     = (const float*)d_in[5];
    float* out = (float*)d_out;

    const int n = in_sizes[0] / FIN;
    const int e = in_sizes[1] / 2;
    const int* src = ei;
    const int* dst = ei + e;

    k_init<<<(n + 255) / 256, 256>>>(n);
    k_gemm<<<(n + 63) / 64, 256>>>(x, W, att_src, att_dst, n);
    k_count<<<(e + 255) / 256, 256>>>(dst, e);
    const int nb = (n + 1023) / 1024;
    k_scanA<<<nb, 256>>>(n);
    k_scanB<<<1, 32>>>(nb, n);
    k_scanC<<<(n + 255) / 256, 256>>>(n);
    k_reorder<<<(e + 255) / 256, 256>>>(src, dst, e);
    k_agg<<<(n * 32 + 255) / 256, 256>>>(bias, out, n);
}